// round 5
// baseline (speedup 1.0000x reference)
#include <cuda_runtime.h>
#include <cuda_bf16.h>
#include <cstdint>
#include <math_constants.h>

#define N_NODES 8192
#define D_FEAT  512
#define KNN     30
#define KP1     31
#define HALF_E  (N_NODES * KP1)   // 253952 directed edges per half

// ---------------- static device scratch (no allocs allowed) ----------------
__device__ float g_xn[(size_t)N_NODES * D_FEAT];          // 16 MB
__device__ float g_sim[(size_t)N_NODES * N_NODES];        // 256 MB
__device__ float g_vals[(size_t)N_NODES * KP1];
__device__ int   g_inds[(size_t)N_NODES * KP1];
__device__ float g_norm[N_NODES];

// ---------------- row normalize: xn = x / ||x||_2 (strict IEEE fp32) --------
__global__ void normalize_kernel(const float* __restrict__ x) {
    int row = blockIdx.x;
    int t   = threadIdx.x;                 // 128 threads, 4 floats each
    const float4* xr = (const float4*)(x + (size_t)row * D_FEAT);
    float4 v = xr[t];
    float ss = v.x * v.x + v.y * v.y + v.z * v.z + v.w * v.w;
    #pragma unroll
    for (int o = 16; o; o >>= 1) ss += __shfl_down_sync(0xffffffffu, ss, o);
    __shared__ float ws[4];
    if ((t & 31) == 0) ws[t >> 5] = ss;
    __syncthreads();
    float nrm = __fsqrt_rn(ws[0] + ws[1] + ws[2] + ws[3]);
    float4 o4;
    o4.x = __fdiv_rn(v.x, nrm); o4.y = __fdiv_rn(v.y, nrm);
    o4.z = __fdiv_rn(v.z, nrm); o4.w = __fdiv_rn(v.w, nrm);
    ((float4*)(g_xn + (size_t)row * D_FEAT))[t] = o4;
}

// ---------------- symmetric fp32 GEMM: sim = xn * xn^T ----------------------
// Each output element = sequential FMA chain over ascending k (matches
// Eigen gebp / cuBLAS SGEMM accumulation order bit-exactly).
#define BM 128
#define BN 128
#define BK 16
__global__ __launch_bounds__(256) void sgemm_sym_kernel() {
    int bx = blockIdx.x, by = blockIdx.y;
    if (bx > by) return;                    // only lower triangle of block grid

    __shared__ float As[BK][BM];
    __shared__ float Bs[BK][BN];

    int t  = threadIdx.x;
    int tx = t & 15;          // 16 cols of threads
    int ty = t >> 4;          // 16 rows of threads

    const float* Aoff = g_xn + (size_t)(by * BM) * D_FEAT;
    const float* Boff = g_xn + (size_t)(bx * BM) * D_FEAT;

    float acc[8][8];
    #pragma unroll
    for (int i = 0; i < 8; i++)
        #pragma unroll
        for (int j = 0; j < 8; j++) acc[i][j] = 0.f;

    for (int k0 = 0; k0 < D_FEAT; k0 += BK) {
        #pragma unroll
        for (int it = 0; it < 2; it++) {
            int idx = t + it * 256;        // 0..511  (512 float4 per tile)
            int r   = idx >> 2;            // 0..127
            int c4  = (idx & 3) * 4;       // 0,4,8,12
            float4 va = *(const float4*)&Aoff[(size_t)r * D_FEAT + k0 + c4];
            As[c4 + 0][r] = va.x; As[c4 + 1][r] = va.y;
            As[c4 + 2][r] = va.z; As[c4 + 3][r] = va.w;
            float4 vb = *(const float4*)&Boff[(size_t)r * D_FEAT + k0 + c4];
            Bs[c4 + 0][r] = vb.x; Bs[c4 + 1][r] = vb.y;
            Bs[c4 + 2][r] = vb.z; Bs[c4 + 3][r] = vb.w;
        }
        __syncthreads();
        #pragma unroll
        for (int kk = 0; kk < BK; kk++) {
            float a[8], b[8];
            *(float4*)(a)     = *(const float4*)&As[kk][ty * 8];
            *(float4*)(a + 4) = *(const float4*)&As[kk][ty * 8 + 4];
            *(float4*)(b)     = *(const float4*)&Bs[kk][tx * 8];
            *(float4*)(b + 4) = *(const float4*)&Bs[kk][tx * 8 + 4];
            #pragma unroll
            for (int i = 0; i < 8; i++)
                #pragma unroll
                for (int j = 0; j < 8; j++)
                    acc[i][j] = fmaf(a[i], b[j], acc[i][j]);
        }
        __syncthreads();
    }

    size_t rowbase = (size_t)(by * BM + ty * 8);
    size_t colbase = (size_t)(bx * BM + tx * 8);

    #pragma unroll
    for (int i = 0; i < 8; i++) {
        float4* p = (float4*)&g_sim[(rowbase + i) * N_NODES + colbase];
        p[0] = make_float4(acc[i][0], acc[i][1], acc[i][2], acc[i][3]);
        p[1] = make_float4(acc[i][4], acc[i][5], acc[i][6], acc[i][7]);
    }
    if (bx != by) {
        #pragma unroll
        for (int j = 0; j < 8; j++) {
            float4* p = (float4*)&g_sim[(colbase + j) * N_NODES + rowbase];
            p[0] = make_float4(acc[0][j], acc[1][j], acc[2][j], acc[3][j]);
            p[1] = make_float4(acc[4][j], acc[5][j], acc[6][j], acc[7][j]);
        }
    }
}

// ---------------- per-row top-31 (sorted desc, ties -> lower index) ----------
__global__ __launch_bounds__(256) void topk_kernel() {
    __shared__ float sv[N_NODES];
    __shared__ float wv[8];
    __shared__ int   wi[8];
    __shared__ int   win_i;

    int row = blockIdx.x;
    int t   = threadIdx.x;
    int lane = t & 31, warp = t >> 5;

    const float4* srow = (const float4*)(g_sim + (size_t)row * N_NODES);
    for (int j = t; j < N_NODES / 4; j += 256) ((float4*)sv)[j] = srow[j];
    __syncthreads();

    float bv = -CUDART_INF_F;
    int   bi = 0x7fffffff;
    #pragma unroll
    for (int m = 0; m < 32; m++) {
        int j = t + 256 * m;
        float v = sv[j];
        if (v > bv || (v == bv && j < bi)) { bv = v; bi = j; }
    }

    for (int p = 0; p < KP1; p++) {
        float rv = bv; int ri = bi;
        #pragma unroll
        for (int o = 16; o; o >>= 1) {
            float ov = __shfl_down_sync(0xffffffffu, rv, o);
            int   oi = __shfl_down_sync(0xffffffffu, ri, o);
            if (ov > rv || (ov == rv && oi < ri)) { rv = ov; ri = oi; }
        }
        if (lane == 0) { wv[warp] = rv; wi[warp] = ri; }
        __syncthreads();
        if (t == 0) {
            float fv = wv[0]; int fi = wi[0];
            #pragma unroll
            for (int w = 1; w < 8; w++) {
                float ov = wv[w]; int oi = wi[w];
                if (ov > fv || (ov == fv && oi < fi)) { fv = ov; fi = oi; }
            }
            win_i = fi;
            g_vals[row * KP1 + p] = fv;
            g_inds[row * KP1 + p] = fi;
        }
        __syncthreads();
        int wj = win_i;
        if ((wj & 255) == t) {
            sv[wj] = -CUDART_INF_F;
            bv = -CUDART_INF_F; bi = 0x7fffffff;
            #pragma unroll
            for (int m = 0; m < 32; m++) {
                int j = t + 256 * m;
                float v = sv[j];
                if (v > bv || (v == bv && j < bi)) { bv = v; bi = j; }
            }
        }
        __syncthreads();
    }
}

// ---------------- degree mass: norm = row-sum + col scatter-sum --------------
__global__ void zero_norm_kernel() {
    int i = blockIdx.x * blockDim.x + threadIdx.x;
    if (i < N_NODES) g_norm[i] = 0.f;
}
__global__ void norm_accum_kernel() {
    int i = blockIdx.x * blockDim.x + threadIdx.x;
    if (i >= HALF_E) return;
    int   r = i / KP1;
    int   c = g_inds[i];
    float v = g_vals[i];
    atomicAdd(&g_norm[r], v);
    atomicAdd(&g_norm[c], v);
}

// ---------------- zero 256MB adjacency ----------------
__global__ void zero_adj_kernel(float* __restrict__ adj) {
    size_t i = (size_t)blockIdx.x * blockDim.x + threadIdx.x;
    ((float4*)adj)[i] = make_float4(0.f, 0.f, 0.f, 0.f);
}

// ---------------- JAX threefry2x32, key = (0, 42) ----------------
__device__ __forceinline__ uint32_t rotl32(uint32_t v, int d) {
    return (v << d) | (v >> (32 - d));
}
__device__ __forceinline__ void threefry2x32_42(uint32_t c0, uint32_t c1,
                                                uint32_t& o0, uint32_t& o1) {
    const uint32_t ks0 = 0u, ks1 = 42u, ks2 = 0u ^ 42u ^ 0x1BD11BDAu;
    uint32_t x0 = c0 + ks0, x1 = c1 + ks1;
    const int ra[4] = {13, 15, 26, 6};
    const int rb[4] = {17, 29, 16, 24};
    #pragma unroll
    for (int i = 0; i < 4; i++) { x0 += x1; x1 = rotl32(x1, ra[i]); x1 ^= x0; }
    x0 += ks1; x1 += ks2 + 1u;
    #pragma unroll
    for (int i = 0; i < 4; i++) { x0 += x1; x1 = rotl32(x1, rb[i]); x1 ^= x0; }
    x0 += ks2; x1 += ks0 + 2u;
    #pragma unroll
    for (int i = 0; i < 4; i++) { x0 += x1; x1 = rotl32(x1, ra[i]); x1 ^= x0; }
    x0 += ks0; x1 += ks1 + 3u;
    #pragma unroll
    for (int i = 0; i < 4; i++) { x0 += x1; x1 = rotl32(x1, rb[i]); x1 ^= x0; }
    x0 += ks1; x1 += ks2 + 4u;
    #pragma unroll
    for (int i = 0; i < 4; i++) { x0 += x1; x1 = rotl32(x1, ra[i]); x1 ^= x0; }
    x0 += ks2; x1 += ks0 + 5u;
    o0 = x0; o1 = x1;
}

// jax_threefry_partitionable (default since 0.4.36) 32-bit path:
//   ctr = (hi32(i), lo32(i)) = (0, i);  bits[i] = out0 ^ out1
__device__ __forceinline__ bool keep_edge(uint32_t i) {
    uint32_t o0, o1;
    threefry2x32_42(0u, i, o0, o1);
    uint32_t b = o0 ^ o1;
    float u = __uint_as_float((b >> 9) | 0x3f800000u) - 1.0f;
    return u < 0.9f;
}

// ---------------- normalize edges + dropout + symmetric scatter-add ----------
__global__ void scatter_kernel(float* __restrict__ adj) {
    int i = blockIdx.x * blockDim.x + threadIdx.x;
    if (i >= HALF_E) return;
    int   r = i / KP1;
    int   c = g_inds[i];
    float v = g_vals[i];
    float w = v * __frcp_rn(__fsqrt_rn(g_norm[r]));
    w = w * __frcp_rn(__fsqrt_rn(g_norm[c]));
    if (isnan(w)) w = 0.f;
    w = fmaxf(w, 0.f);                       // relu (both directions)

    float w0 = keep_edge((uint32_t)i)            ? (w / 0.9f) : 0.f;  // (r,c)
    float w1 = keep_edge((uint32_t)(i + HALF_E)) ? (w / 0.9f) : 0.f;  // (c,r)

    atomicAdd(&adj[(size_t)r * N_NODES + c], w0);
    atomicAdd(&adj[(size_t)c * N_NODES + r], w1);
}

// ---------------- launch ----------------
extern "C" void kernel_launch(void* const* d_in, const int* in_sizes, int n_in,
                              void* d_out, int out_size) {
    const float* x  = (const float*)d_in[0];
    float* adj = (float*)d_out;
    (void)in_sizes; (void)n_in; (void)out_size;   // k fixed at 30 for this problem

    normalize_kernel<<<N_NODES, 128>>>(x);

    dim3 ggrid(N_NODES / BN, N_NODES / BM);
    sgemm_sym_kernel<<<ggrid, 256>>>();

    topk_kernel<<<N_NODES, 256>>>();

    zero_norm_kernel<<<(N_NODES + 255) / 256, 256>>>();
    norm_accum_kernel<<<(HALF_E + 255) / 256, 256>>>();

    zero_adj_kernel<<<(N_NODES * (N_NODES / 4)) / 256, 256>>>(adj);
    scatter_kernel<<<(HALF_E + 255) / 256, 256>>>(adj);
}

// round 6
// speedup vs baseline: 1.0226x; 1.0226x over previous
#include <cuda_runtime.h>
#include <cuda_bf16.h>
#include <cstdint>
#include <math_constants.h>

#define N_NODES 8192
#define D_FEAT  512
#define KNN     30
#define KP1     31
#define HALF_E  (N_NODES * KP1)   // 253952 directed edges per half

// ---------------- static device scratch (no allocs allowed) ----------------
__device__ float g_xn[(size_t)N_NODES * D_FEAT];          // 16 MB
__device__ float g_sim[(size_t)N_NODES * N_NODES];        // 256 MB
__device__ float g_vals[(size_t)N_NODES * KP1];
__device__ int   g_inds[(size_t)N_NODES * KP1];
__device__ float g_norm[N_NODES];

// ---------------- row normalize: xn = x / ||x||_2 (strict IEEE fp32) --------
// also zeroes g_norm (merged zero_norm kernel)
__global__ void normalize_kernel(const float* __restrict__ x) {
    int row = blockIdx.x;
    int t   = threadIdx.x;                 // 128 threads, 4 floats each
    if (t == 0) g_norm[row] = 0.f;
    const float4* xr = (const float4*)(x + (size_t)row * D_FEAT);
    float4 v = xr[t];
    float ss = v.x * v.x + v.y * v.y + v.z * v.z + v.w * v.w;
    #pragma unroll
    for (int o = 16; o; o >>= 1) ss += __shfl_down_sync(0xffffffffu, ss, o);
    __shared__ float ws[4];
    if ((t & 31) == 0) ws[t >> 5] = ss;
    __syncthreads();
    float nrm = __fsqrt_rn(ws[0] + ws[1] + ws[2] + ws[3]);
    float4 o4;
    o4.x = __fdiv_rn(v.x, nrm); o4.y = __fdiv_rn(v.y, nrm);
    o4.z = __fdiv_rn(v.z, nrm); o4.w = __fdiv_rn(v.w, nrm);
    ((float4*)(g_xn + (size_t)row * D_FEAT))[t] = o4;
}

// ---------------- symmetric fp32 GEMM: sim = xn * xn^T ----------------------
// Packed fma.rn.f32x2 (2 IEEE FMAs/instr) — bit-identical per-element
// sequential FMA chain over ascending k, at 2x FFMA issue throughput.
#define BM 128
#define BN 128
#define BK 16

__device__ __forceinline__ unsigned long long pack_dup(float a) {
    unsigned long long r;
    asm("mov.b64 %0, {%1, %1};" : "=l"(r) : "f"(a));
    return r;
}
__device__ __forceinline__ void fma_f32x2(unsigned long long& acc,
                                          unsigned long long a,
                                          unsigned long long b) {
    asm("fma.rn.f32x2 %0, %1, %2, %0;" : "+l"(acc) : "l"(a), "l"(b));
}

__global__ __launch_bounds__(256) void sgemm_sym_kernel() {
    int bx = blockIdx.x, by = blockIdx.y;
    if (bx > by) return;                    // only lower triangle of block grid

    __shared__ float As[BK][BM];
    __shared__ float Bs[BK][BN];

    int t  = threadIdx.x;
    int tx = t & 15;          // 16 cols of threads
    int ty = t >> 4;          // 16 rows of threads

    const float* Aoff = g_xn + (size_t)(by * BM) * D_FEAT;
    const float* Boff = g_xn + (size_t)(bx * BM) * D_FEAT;

    // acc2[i][jp]: packed pair of accumulators for cols (2*jp, 2*jp+1)
    unsigned long long acc2[8][4];
    #pragma unroll
    for (int i = 0; i < 8; i++)
        #pragma unroll
        for (int j = 0; j < 4; j++) acc2[i][j] = 0ull;

    for (int k0 = 0; k0 < D_FEAT; k0 += BK) {
        #pragma unroll
        for (int it = 0; it < 2; it++) {
            int idx = t + it * 256;        // 0..511  (512 float4 per tile)
            int r   = idx >> 2;            // 0..127
            int c4  = (idx & 3) * 4;       // 0,4,8,12
            float4 va = *(const float4*)&Aoff[(size_t)r * D_FEAT + k0 + c4];
            As[c4 + 0][r] = va.x; As[c4 + 1][r] = va.y;
            As[c4 + 2][r] = va.z; As[c4 + 3][r] = va.w;
            float4 vb = *(const float4*)&Boff[(size_t)r * D_FEAT + k0 + c4];
            Bs[c4 + 0][r] = vb.x; Bs[c4 + 1][r] = vb.y;
            Bs[c4 + 2][r] = vb.z; Bs[c4 + 3][r] = vb.w;
        }
        __syncthreads();
        #pragma unroll
        for (int kk = 0; kk < BK; kk++) {
            float a[8];
            *(float4*)(a)     = *(const float4*)&As[kk][ty * 8];
            *(float4*)(a + 4) = *(const float4*)&As[kk][ty * 8 + 4];
            // b pairs: (Bs[kk][tx*8+2j], Bs[kk][tx*8+2j+1]) as 64-bit lanes
            unsigned long long b2[4];
            const unsigned long long* brow =
                (const unsigned long long*)&Bs[kk][tx * 8];
            #pragma unroll
            for (int j = 0; j < 4; j++) b2[j] = brow[j];
            unsigned long long ad[8];
            #pragma unroll
            for (int i = 0; i < 8; i++) ad[i] = pack_dup(a[i]);
            #pragma unroll
            for (int i = 0; i < 8; i++)
                #pragma unroll
                for (int j = 0; j < 4; j++)
                    fma_f32x2(acc2[i][j], ad[i], b2[j]);
        }
        __syncthreads();
    }

    size_t rowbase = (size_t)(by * BM + ty * 8);
    size_t colbase = (size_t)(bx * BM + tx * 8);

    // unpack: low 32 bits of acc2[i][j] = col 2j, high = col 2j+1
    float accf[8][8];
    #pragma unroll
    for (int i = 0; i < 8; i++)
        #pragma unroll
        for (int j = 0; j < 4; j++) {
            uint32_t lo, hi;
            asm("mov.b64 {%0, %1}, %2;" : "=r"(lo), "=r"(hi) : "l"(acc2[i][j]));
            accf[i][2 * j]     = __uint_as_float(lo);
            accf[i][2 * j + 1] = __uint_as_float(hi);
        }

    #pragma unroll
    for (int i = 0; i < 8; i++) {
        float4* p = (float4*)&g_sim[(rowbase + i) * N_NODES + colbase];
        p[0] = make_float4(accf[i][0], accf[i][1], accf[i][2], accf[i][3]);
        p[1] = make_float4(accf[i][4], accf[i][5], accf[i][6], accf[i][7]);
    }
    if (bx != by) {
        #pragma unroll
        for (int j = 0; j < 8; j++) {
            float4* p = (float4*)&g_sim[(colbase + j) * N_NODES + rowbase];
            p[0] = make_float4(accf[0][j], accf[1][j], accf[2][j], accf[3][j]);
            p[1] = make_float4(accf[4][j], accf[5][j], accf[6][j], accf[7][j]);
        }
    }
}

// ---------------- per-row top-31 (sorted desc, ties -> lower index) ----------
__global__ __launch_bounds__(256) void topk_kernel() {
    __shared__ float sv[N_NODES];
    __shared__ float wv[8];
    __shared__ int   wi[8];
    __shared__ int   win_i;

    int row = blockIdx.x;
    int t   = threadIdx.x;
    int lane = t & 31, warp = t >> 5;

    const float4* srow = (const float4*)(g_sim + (size_t)row * N_NODES);
    for (int j = t; j < N_NODES / 4; j += 256) ((float4*)sv)[j] = srow[j];
    __syncthreads();

    float bv = -CUDART_INF_F;
    int   bi = 0x7fffffff;
    #pragma unroll
    for (int m = 0; m < 32; m++) {
        int j = t + 256 * m;
        float v = sv[j];
        if (v > bv || (v == bv && j < bi)) { bv = v; bi = j; }
    }

    for (int p = 0; p < KP1; p++) {
        float rv = bv; int ri = bi;
        #pragma unroll
        for (int o = 16; o; o >>= 1) {
            float ov = __shfl_down_sync(0xffffffffu, rv, o);
            int   oi = __shfl_down_sync(0xffffffffu, ri, o);
            if (ov > rv || (ov == rv && oi < ri)) { rv = ov; ri = oi; }
        }
        if (lane == 0) { wv[warp] = rv; wi[warp] = ri; }
        __syncthreads();
        if (t == 0) {
            float fv = wv[0]; int fi = wi[0];
            #pragma unroll
            for (int w = 1; w < 8; w++) {
                float ov = wv[w]; int oi = wi[w];
                if (ov > fv || (ov == fv && oi < fi)) { fv = ov; fi = oi; }
            }
            win_i = fi;
            g_vals[row * KP1 + p] = fv;
            g_inds[row * KP1 + p] = fi;
        }
        __syncthreads();
        int wj = win_i;
        if ((wj & 255) == t) {
            sv[wj] = -CUDART_INF_F;
            bv = -CUDART_INF_F; bi = 0x7fffffff;
            #pragma unroll
            for (int m = 0; m < 32; m++) {
                int j = t + 256 * m;
                float v = sv[j];
                if (v > bv || (v == bv && j < bi)) { bv = v; bi = j; }
            }
        }
        __syncthreads();
    }
}

// ---------------- degree mass: norm = row-sum + col scatter-sum --------------
__global__ void norm_accum_kernel() {
    int i = blockIdx.x * blockDim.x + threadIdx.x;
    if (i >= HALF_E) return;
    int   r = i / KP1;
    int   c = g_inds[i];
    float v = g_vals[i];
    atomicAdd(&g_norm[r], v);
    atomicAdd(&g_norm[c], v);
}

// ---------------- zero 256MB adjacency ----------------
__global__ void zero_adj_kernel(float* __restrict__ adj) {
    size_t i = (size_t)blockIdx.x * blockDim.x + threadIdx.x;
    ((float4*)adj)[i] = make_float4(0.f, 0.f, 0.f, 0.f);
}

// ---------------- JAX threefry2x32, key = (0, 42) ----------------
__device__ __forceinline__ uint32_t rotl32(uint32_t v, int d) {
    return (v << d) | (v >> (32 - d));
}
__device__ __forceinline__ void threefry2x32_42(uint32_t c0, uint32_t c1,
                                                uint32_t& o0, uint32_t& o1) {
    const uint32_t ks0 = 0u, ks1 = 42u, ks2 = 0u ^ 42u ^ 0x1BD11BDAu;
    uint32_t x0 = c0 + ks0, x1 = c1 + ks1;
    const int ra[4] = {13, 15, 26, 6};
    const int rb[4] = {17, 29, 16, 24};
    #pragma unroll
    for (int i = 0; i < 4; i++) { x0 += x1; x1 = rotl32(x1, ra[i]); x1 ^= x0; }
    x0 += ks1; x1 += ks2 + 1u;
    #pragma unroll
    for (int i = 0; i < 4; i++) { x0 += x1; x1 = rotl32(x1, rb[i]); x1 ^= x0; }
    x0 += ks2; x1 += ks0 + 2u;
    #pragma unroll
    for (int i = 0; i < 4; i++) { x0 += x1; x1 = rotl32(x1, ra[i]); x1 ^= x0; }
    x0 += ks0; x1 += ks1 + 3u;
    #pragma unroll
    for (int i = 0; i < 4; i++) { x0 += x1; x1 = rotl32(x1, rb[i]); x1 ^= x0; }
    x0 += ks1; x1 += ks2 + 4u;
    #pragma unroll
    for (int i = 0; i < 4; i++) { x0 += x1; x1 = rotl32(x1, ra[i]); x1 ^= x0; }
    x0 += ks2; x1 += ks0 + 5u;
    o0 = x0; o1 = x1;
}

// jax_threefry_partitionable (default since 0.4.36) 32-bit path:
//   ctr = (hi32(i), lo32(i)) = (0, i);  bits[i] = out0 ^ out1
__device__ __forceinline__ bool keep_edge(uint32_t i) {
    uint32_t o0, o1;
    threefry2x32_42(0u, i, o0, o1);
    uint32_t b = o0 ^ o1;
    float u = __uint_as_float((b >> 9) | 0x3f800000u) - 1.0f;
    return u < 0.9f;
}

// ---------------- normalize edges + dropout + symmetric scatter-add ----------
__global__ void scatter_kernel(float* __restrict__ adj) {
    int i = blockIdx.x * blockDim.x + threadIdx.x;
    if (i >= HALF_E) return;
    int   r = i / KP1;
    int   c = g_inds[i];
    float v = g_vals[i];
    float w = v * __frcp_rn(__fsqrt_rn(g_norm[r]));
    w = w * __frcp_rn(__fsqrt_rn(g_norm[c]));
    if (isnan(w)) w = 0.f;
    w = fmaxf(w, 0.f);                       // relu (both directions)

    float w0 = keep_edge((uint32_t)i)            ? (w / 0.9f) : 0.f;  // (r,c)
    float w1 = keep_edge((uint32_t)(i + HALF_E)) ? (w / 0.9f) : 0.f;  // (c,r)

    atomicAdd(&adj[(size_t)r * N_NODES + c], w0);
    atomicAdd(&adj[(size_t)c * N_NODES + r], w1);
}

// ---------------- launch ----------------
extern "C" void kernel_launch(void* const* d_in, const int* in_sizes, int n_in,
                              void* d_out, int out_size) {
    const float* x  = (const float*)d_in[0];
    float* adj = (float*)d_out;
    (void)in_sizes; (void)n_in; (void)out_size;   // k fixed at 30 for this problem

    normalize_kernel<<<N_NODES, 128>>>(x);

    dim3 ggrid(N_NODES / BN, N_NODES / BM);
    sgemm_sym_kernel<<<ggrid, 256>>>();

    topk_kernel<<<N_NODES, 256>>>();

    norm_accum_kernel<<<(HALF_E + 255) / 256, 256>>>();

    zero_adj_kernel<<<(N_NODES * (N_NODES / 4)) / 256, 256>>>(adj);
    scatter_kernel<<<(HALF_E + 255) / 256, 256>>>(adj);
}

// round 7
// speedup vs baseline: 1.2960x; 1.2674x over previous
#include <cuda_runtime.h>
#include <cuda_fp16.h>
#include <cuda_bf16.h>
#include <cstdint>
#include <math_constants.h>

#define N_NODES 8192
#define D_FEAT  512
#define KNN     30
#define KP1     31
#define NCAND   40
#define HALF_E  (N_NODES * KP1)   // 253952 directed edges per half

// ---------------- static device scratch (no allocs allowed) ----------------
__device__ float g_xn[(size_t)N_NODES * D_FEAT];                       // 16 MB
__device__ __align__(16) __half g_xh[(size_t)N_NODES * D_FEAT];        // 8 MB
__device__ float g_sim[(size_t)N_NODES * N_NODES];                     // 256 MB (approx)
__device__ int   g_cand[(size_t)N_NODES * NCAND];
__device__ float g_vals[(size_t)N_NODES * KP1];
__device__ int   g_inds[(size_t)N_NODES * KP1];
__device__ float g_norm[N_NODES];

// ---------------- row normalize: xn = x/||x|| (IEEE fp32) + fp16 copy -------
__global__ void normalize_kernel(const float* __restrict__ x) {
    int row = blockIdx.x;
    int t   = threadIdx.x;                 // 128 threads, 4 floats each
    if (t == 0) g_norm[row] = 0.f;
    const float4* xr = (const float4*)(x + (size_t)row * D_FEAT);
    float4 v = xr[t];
    float ss = v.x * v.x + v.y * v.y + v.z * v.z + v.w * v.w;
    #pragma unroll
    for (int o = 16; o; o >>= 1) ss += __shfl_down_sync(0xffffffffu, ss, o);
    __shared__ float ws[4];
    if ((t & 31) == 0) ws[t >> 5] = ss;
    __syncthreads();
    float nrm = __fsqrt_rn(ws[0] + ws[1] + ws[2] + ws[3]);
    float4 o4;
    o4.x = __fdiv_rn(v.x, nrm); o4.y = __fdiv_rn(v.y, nrm);
    o4.z = __fdiv_rn(v.z, nrm); o4.w = __fdiv_rn(v.w, nrm);
    ((float4*)(g_xn + (size_t)row * D_FEAT))[t] = o4;
    __half2* hp = (__half2*)(g_xh + (size_t)row * D_FEAT);
    hp[t * 2]     = __floats2half2_rn(o4.x, o4.y);
    hp[t * 2 + 1] = __floats2half2_rn(o4.z, o4.w);
}

// ------------- approx symmetric GEMM: fp16 HMMA, fp32 accum -----------------
// 128x128 CTA tile, 8 warps (2x4), warp tile 64x32, m16n8k16.
__device__ __forceinline__ void mma16816(float* d, const uint32_t* a, const uint32_t* b) {
    asm volatile(
        "mma.sync.aligned.m16n8k16.row.col.f32.f16.f16.f32 "
        "{%0,%1,%2,%3}, {%4,%5,%6,%7}, {%8,%9}, {%0,%1,%2,%3};"
        : "+f"(d[0]), "+f"(d[1]), "+f"(d[2]), "+f"(d[3])
        : "r"(a[0]), "r"(a[1]), "r"(a[2]), "r"(a[3]), "r"(b[0]), "r"(b[1]));
}

#define HPITCH 20   // half2 per row (40 halves, 32 data + 8 pad)
__global__ __launch_bounds__(256) void hgemm_sym_kernel() {
    int bx = blockIdx.x, by = blockIdx.y;
    if (bx > by) return;                    // lower-triangular block grid

    __shared__ __align__(16) uint32_t As2[128][HPITCH];  // half2 as u32
    __shared__ __align__(16) uint32_t Bs2[128][HPITCH];

    int t = threadIdx.x, lane = t & 31, w = t >> 5;
    int warpM = (w & 1) * 64, warpN = (w >> 1) * 32;
    int qr = lane >> 2, qc = lane & 3;      // quad row / col

    const __half* Ag = g_xh + (size_t)(by * 128) * D_FEAT;
    const __half* Bg = g_xh + (size_t)(bx * 128) * D_FEAT;

    float d[4][4][4];
    #pragma unroll
    for (int i = 0; i < 4; i++)
        #pragma unroll
        for (int j = 0; j < 4; j++)
            #pragma unroll
            for (int c = 0; c < 4; c++) d[i][j][c] = 0.f;

    for (int k0 = 0; k0 < D_FEAT; k0 += 32) {
        __syncthreads();
        #pragma unroll
        for (int it = 0; it < 2; it++) {
            int idx  = t + it * 256;        // 0..511
            int node = idx >> 2;
            int koff = (idx & 3) * 8;       // halves
            uint4 va = *(const uint4*)(Ag + (size_t)node * D_FEAT + k0 + koff);
            *(uint4*)&As2[node][koff >> 1] = va;
            uint4 vb = *(const uint4*)(Bg + (size_t)node * D_FEAT + k0 + koff);
            *(uint4*)&Bs2[node][koff >> 1] = vb;
        }
        __syncthreads();
        #pragma unroll
        for (int kb = 0; kb < 2; kb++) {    // two k16 steps
            int khb = kb * 8;
            uint32_t a[4][4], b[4][2];
            #pragma unroll
            for (int mt = 0; mt < 4; mt++) {
                int m = warpM + mt * 16 + qr;
                a[mt][0] = As2[m][khb + qc];
                a[mt][1] = As2[m + 8][khb + qc];
                a[mt][2] = As2[m][khb + 4 + qc];
                a[mt][3] = As2[m + 8][khb + 4 + qc];
            }
            #pragma unroll
            for (int nt = 0; nt < 4; nt++) {
                int n = warpN + nt * 8 + qr;
                b[nt][0] = Bs2[n][khb + qc];
                b[nt][1] = Bs2[n][khb + 4 + qc];
            }
            #pragma unroll
            for (int mt = 0; mt < 4; mt++)
                #pragma unroll
                for (int nt = 0; nt < 4; nt++)
                    mma16816(d[mt][nt], a[mt], b[nt]);
        }
    }

    // epilogue: write tile + mirrored tile
    #pragma unroll
    for (int mt = 0; mt < 4; mt++) {
        #pragma unroll
        for (int nt = 0; nt < 4; nt++) {
            int r0 = by * 128 + warpM + mt * 16 + qr;
            int c0 = bx * 128 + warpN + nt * 8 + qc * 2;
            *(float2*)&g_sim[(size_t)r0 * N_NODES + c0] =
                make_float2(d[mt][nt][0], d[mt][nt][1]);
            *(float2*)&g_sim[(size_t)(r0 + 8) * N_NODES + c0] =
                make_float2(d[mt][nt][2], d[mt][nt][3]);
            if (bx != by) {
                g_sim[(size_t)c0 * N_NODES + r0]           = d[mt][nt][0];
                g_sim[(size_t)(c0 + 1) * N_NODES + r0]     = d[mt][nt][1];
                g_sim[(size_t)c0 * N_NODES + r0 + 8]       = d[mt][nt][2];
                g_sim[(size_t)(c0 + 1) * N_NODES + r0 + 8] = d[mt][nt][3];
            }
        }
    }
}

// ------------- per-row approx top-40 candidate selection --------------------
__global__ __launch_bounds__(256) void topk_kernel() {
    __shared__ float sv[N_NODES];
    __shared__ float wv[8];
    __shared__ int   wi[8];
    __shared__ int   win_i;

    int row = blockIdx.x;
    int t   = threadIdx.x;
    int lane = t & 31, warp = t >> 5;

    const float4* srow = (const float4*)(g_sim + (size_t)row * N_NODES);
    for (int j = t; j < N_NODES / 4; j += 256) ((float4*)sv)[j] = srow[j];
    __syncthreads();

    float bv = -CUDART_INF_F;
    int   bi = 0x7fffffff;
    #pragma unroll
    for (int m = 0; m < 32; m++) {
        int j = t + 256 * m;
        float v = sv[j];
        if (v > bv || (v == bv && j < bi)) { bv = v; bi = j; }
    }

    for (int p = 0; p < NCAND; p++) {
        float rv = bv; int ri = bi;
        #pragma unroll
        for (int o = 16; o; o >>= 1) {
            float ov = __shfl_down_sync(0xffffffffu, rv, o);
            int   oi = __shfl_down_sync(0xffffffffu, ri, o);
            if (ov > rv || (ov == rv && oi < ri)) { rv = ov; ri = oi; }
        }
        if (lane == 0) { wv[warp] = rv; wi[warp] = ri; }
        __syncthreads();
        if (t == 0) {
            float fv = wv[0]; int fi = wi[0];
            #pragma unroll
            for (int w2 = 1; w2 < 8; w2++) {
                float ov = wv[w2]; int oi = wi[w2];
                if (ov > fv || (ov == fv && oi < fi)) { fv = ov; fi = oi; }
            }
            win_i = fi;
            g_cand[row * NCAND + p] = fi;
        }
        __syncthreads();
        int wj = win_i;
        if ((wj & 255) == t) {
            sv[wj] = -CUDART_INF_F;
            bv = -CUDART_INF_F; bi = 0x7fffffff;
            #pragma unroll
            for (int m = 0; m < 32; m++) {
                int j = t + 256 * m;
                float v = sv[j];
                if (v > bv || (v == bv && j < bi)) { bv = v; bi = j; }
            }
        }
        __syncthreads();
    }
}

// ------------- exact rescore (bit-exact ascending-k chain) + exact top-31 ---
__global__ __launch_bounds__(256) void rescore_kernel() {
    __shared__ float srow[D_FEAT];
    __shared__ float scol[20][D_FEAT + 1];
    __shared__ float cval[NCAND];
    __shared__ int   ccol[NCAND];

    int row = blockIdx.x;
    int t   = threadIdx.x;

    if (t < 128) ((float4*)srow)[t] = ((const float4*)(g_xn + (size_t)row * D_FEAT))[t];
    if (t < NCAND) ccol[t] = g_cand[row * NCAND + t];

    #pragma unroll
    for (int batch = 0; batch < 2; batch++) {
        __syncthreads();
        for (int i = t; i < 20 * (D_FEAT / 4); i += 256) {
            int ci  = i / (D_FEAT / 4);
            int off = i % (D_FEAT / 4);
            int c   = ccol[batch * 20 + ci];
            float4 v = ((const float4*)(g_xn + (size_t)c * D_FEAT))[off];
            scol[ci][off * 4 + 0] = v.x; scol[ci][off * 4 + 1] = v.y;
            scol[ci][off * 4 + 2] = v.z; scol[ci][off * 4 + 3] = v.w;
        }
        __syncthreads();
        if (t < 20) {
            float acc = 0.f;
            #pragma unroll 8
            for (int k = 0; k < D_FEAT; k++)
                acc = fmaf(srow[k], scol[t][k], acc);   // bit-exact sequential chain
            cval[batch * 20 + t] = acc;
        }
    }
    __syncthreads();

    // exact top-31 among 40: (value desc, column asc); warp 0 only
    if (t < 32) {
        for (int p = 0; p < KP1; p++) {
            float v0 = cval[t];           int c0 = ccol[t],      s0 = t;
            float v1 = (t < 8) ? cval[t + 32] : -CUDART_INF_F;
            int   c1 = (t < 8) ? ccol[t + 32] : 0x7fffffff;
            int   s1 = t + 32;
            float bv; int bc, bs;
            if (v0 > v1 || (v0 == v1 && c0 < c1)) { bv = v0; bc = c0; bs = s0; }
            else                                  { bv = v1; bc = c1; bs = s1; }
            #pragma unroll
            for (int o = 16; o; o >>= 1) {
                float ov = __shfl_down_sync(0xffffffffu, bv, o);
                int   oc = __shfl_down_sync(0xffffffffu, bc, o);
                int   os = __shfl_down_sync(0xffffffffu, bs, o);
                if (ov > bv || (ov == bv && oc < bc)) { bv = ov; bc = oc; bs = os; }
            }
            bv = __shfl_sync(0xffffffffu, bv, 0);
            bc = __shfl_sync(0xffffffffu, bc, 0);
            bs = __shfl_sync(0xffffffffu, bs, 0);
            if (t == 0) {
                g_vals[row * KP1 + p] = bv;
                g_inds[row * KP1 + p] = bc;
                cval[bs] = -CUDART_INF_F;
            }
            __syncwarp();
        }
    }
}

// ---------------- degree mass: norm = row-sum + col scatter-sum --------------
__global__ void norm_accum_kernel() {
    int i = blockIdx.x * blockDim.x + threadIdx.x;
    if (i >= HALF_E) return;
    int   r = i / KP1;
    int   c = g_inds[i];
    float v = g_vals[i];
    atomicAdd(&g_norm[r], v);
    atomicAdd(&g_norm[c], v);
}

// ---------------- zero 256MB adjacency ----------------
__global__ void zero_adj_kernel(float* __restrict__ adj) {
    size_t i = (size_t)blockIdx.x * blockDim.x + threadIdx.x;
    ((float4*)adj)[i] = make_float4(0.f, 0.f, 0.f, 0.f);
}

// ---------------- JAX threefry2x32, key = (0, 42) ----------------
__device__ __forceinline__ uint32_t rotl32(uint32_t v, int d) {
    return (v << d) | (v >> (32 - d));
}
__device__ __forceinline__ void threefry2x32_42(uint32_t c0, uint32_t c1,
                                                uint32_t& o0, uint32_t& o1) {
    const uint32_t ks0 = 0u, ks1 = 42u, ks2 = 0u ^ 42u ^ 0x1BD11BDAu;
    uint32_t x0 = c0 + ks0, x1 = c1 + ks1;
    const int ra[4] = {13, 15, 26, 6};
    const int rb[4] = {17, 29, 16, 24};
    #pragma unroll
    for (int i = 0; i < 4; i++) { x0 += x1; x1 = rotl32(x1, ra[i]); x1 ^= x0; }
    x0 += ks1; x1 += ks2 + 1u;
    #pragma unroll
    for (int i = 0; i < 4; i++) { x0 += x1; x1 = rotl32(x1, rb[i]); x1 ^= x0; }
    x0 += ks2; x1 += ks0 + 2u;
    #pragma unroll
    for (int i = 0; i < 4; i++) { x0 += x1; x1 = rotl32(x1, ra[i]); x1 ^= x0; }
    x0 += ks0; x1 += ks1 + 3u;
    #pragma unroll
    for (int i = 0; i < 4; i++) { x0 += x1; x1 = rotl32(x1, rb[i]); x1 ^= x0; }
    x0 += ks1; x1 += ks2 + 4u;
    #pragma unroll
    for (int i = 0; i < 4; i++) { x0 += x1; x1 = rotl32(x1, ra[i]); x1 ^= x0; }
    x0 += ks2; x1 += ks0 + 5u;
    o0 = x0; o1 = x1;
}

// jax_threefry_partitionable 32-bit path: ctr=(0,i); bits = out0 ^ out1
__device__ __forceinline__ bool keep_edge(uint32_t i) {
    uint32_t o0, o1;
    threefry2x32_42(0u, i, o0, o1);
    uint32_t b = o0 ^ o1;
    float u = __uint_as_float((b >> 9) | 0x3f800000u) - 1.0f;
    return u < 0.9f;
}

// ---------------- normalize edges + dropout + symmetric scatter-add ----------
__global__ void scatter_kernel(float* __restrict__ adj) {
    int i = blockIdx.x * blockDim.x + threadIdx.x;
    if (i >= HALF_E) return;
    int   r = i / KP1;
    int   c = g_inds[i];
    float v = g_vals[i];
    float w = v * __frcp_rn(__fsqrt_rn(g_norm[r]));
    w = w * __frcp_rn(__fsqrt_rn(g_norm[c]));
    if (isnan(w)) w = 0.f;
    w = fmaxf(w, 0.f);                       // relu (both directions)

    float w0 = keep_edge((uint32_t)i)            ? (w / 0.9f) : 0.f;  // (r,c)
    float w1 = keep_edge((uint32_t)(i + HALF_E)) ? (w / 0.9f) : 0.f;  // (c,r)

    atomicAdd(&adj[(size_t)r * N_NODES + c], w0);
    atomicAdd(&adj[(size_t)c * N_NODES + r], w1);
}

// ---------------- launch ----------------
extern "C" void kernel_launch(void* const* d_in, const int* in_sizes, int n_in,
                              void* d_out, int out_size) {
    const float* x  = (const float*)d_in[0];
    float* adj = (float*)d_out;
    (void)in_sizes; (void)n_in; (void)out_size;   // k fixed at 30

    normalize_kernel<<<N_NODES, 128>>>(x);

    dim3 ggrid(N_NODES / 128, N_NODES / 128);
    hgemm_sym_kernel<<<ggrid, 256>>>();

    topk_kernel<<<N_NODES, 256>>>();
    rescore_kernel<<<N_NODES, 256>>>();

    norm_accum_kernel<<<(HALF_E + 255) / 256, 256>>>();

    zero_adj_kernel<<<(N_NODES * (N_NODES / 4)) / 256, 256>>>(adj);
    scatter_kernel<<<(HALF_E + 255) / 256, 256>>>(adj);
}

// round 8
// speedup vs baseline: 2.5083x; 1.9355x over previous
#include <cuda_runtime.h>
#include <cuda_fp16.h>
#include <cuda_bf16.h>
#include <cstdint>
#include <math_constants.h>

#define N_NODES 8192
#define D_FEAT  512
#define KNN     30
#define KP1     31
#define NTGT    40      // approx-rank margin target
#define NCAP    64      // candidate array capacity
#define HALF_E  (N_NODES * KP1)

// ---------------- static device scratch (no allocs allowed) ----------------
__device__ float  g_xn[(size_t)N_NODES * D_FEAT];                     // 16 MB
__device__ __align__(16) __half g_xh[(size_t)N_NODES * D_FEAT];       // 8 MB
__device__ __align__(16) __half g_simh[(size_t)N_NODES * N_NODES];    // 128 MB
__device__ int    g_cand[(size_t)N_NODES * NCAP];
__device__ int    g_ccnt[N_NODES];
__device__ float  g_vals[(size_t)N_NODES * KP1];
__device__ int    g_inds[(size_t)N_NODES * KP1];
__device__ float  g_norm[N_NODES];

// ---------------- row normalize: xn = x/||x|| (IEEE fp32) + fp16 copy -------
__global__ void normalize_kernel(const float* __restrict__ x) {
    int row = blockIdx.x;
    int t   = threadIdx.x;                 // 128 threads, 4 floats each
    if (t == 0) g_norm[row] = 0.f;
    const float4* xr = (const float4*)(x + (size_t)row * D_FEAT);
    float4 v = xr[t];
    float ss = v.x * v.x + v.y * v.y + v.z * v.z + v.w * v.w;
    #pragma unroll
    for (int o = 16; o; o >>= 1) ss += __shfl_down_sync(0xffffffffu, ss, o);
    __shared__ float ws[4];
    if ((t & 31) == 0) ws[t >> 5] = ss;
    __syncthreads();
    float nrm = __fsqrt_rn(ws[0] + ws[1] + ws[2] + ws[3]);
    float4 o4;
    o4.x = __fdiv_rn(v.x, nrm); o4.y = __fdiv_rn(v.y, nrm);
    o4.z = __fdiv_rn(v.z, nrm); o4.w = __fdiv_rn(v.w, nrm);
    ((float4*)(g_xn + (size_t)row * D_FEAT))[t] = o4;
    __half2* hp = (__half2*)(g_xh + (size_t)row * D_FEAT);
    hp[t * 2]     = __floats2half2_rn(o4.x, o4.y);
    hp[t * 2 + 1] = __floats2half2_rn(o4.z, o4.w);
}

// ------------- approx symmetric GEMM: fp16 HMMA, fp32 accum, fp16 out -------
__device__ __forceinline__ void mma16816(float* d, const uint32_t* a, const uint32_t* b) {
    asm volatile(
        "mma.sync.aligned.m16n8k16.row.col.f32.f16.f16.f32 "
        "{%0,%1,%2,%3}, {%4,%5,%6,%7}, {%8,%9}, {%0,%1,%2,%3};"
        : "+f"(d[0]), "+f"(d[1]), "+f"(d[2]), "+f"(d[3])
        : "r"(a[0]), "r"(a[1]), "r"(a[2]), "r"(a[3]), "r"(b[0]), "r"(b[1]));
}

#define HPITCH 20
__global__ __launch_bounds__(256) void hgemm_sym_kernel() {
    int bx = blockIdx.x, by = blockIdx.y;
    if (bx > by) return;

    __shared__ __align__(16) uint32_t As2[128][HPITCH];
    __shared__ __align__(16) uint32_t Bs2[128][HPITCH];

    int t = threadIdx.x, lane = t & 31, w = t >> 5;
    int warpM = (w & 1) * 64, warpN = (w >> 1) * 32;
    int qr = lane >> 2, qc = lane & 3;

    const __half* Ag = g_xh + (size_t)(by * 128) * D_FEAT;
    const __half* Bg = g_xh + (size_t)(bx * 128) * D_FEAT;

    float d[4][4][4];
    #pragma unroll
    for (int i = 0; i < 4; i++)
        #pragma unroll
        for (int j = 0; j < 4; j++)
            #pragma unroll
            for (int c = 0; c < 4; c++) d[i][j][c] = 0.f;

    for (int k0 = 0; k0 < D_FEAT; k0 += 32) {
        __syncthreads();
        #pragma unroll
        for (int it = 0; it < 2; it++) {
            int idx  = t + it * 256;
            int node = idx >> 2;
            int koff = (idx & 3) * 8;
            uint4 va = *(const uint4*)(Ag + (size_t)node * D_FEAT + k0 + koff);
            *(uint4*)&As2[node][koff >> 1] = va;
            uint4 vb = *(const uint4*)(Bg + (size_t)node * D_FEAT + k0 + koff);
            *(uint4*)&Bs2[node][koff >> 1] = vb;
        }
        __syncthreads();
        #pragma unroll
        for (int kb = 0; kb < 2; kb++) {
            int khb = kb * 8;
            uint32_t a[4][4], b[4][2];
            #pragma unroll
            for (int mt = 0; mt < 4; mt++) {
                int m = warpM + mt * 16 + qr;
                a[mt][0] = As2[m][khb + qc];
                a[mt][1] = As2[m + 8][khb + qc];
                a[mt][2] = As2[m][khb + 4 + qc];
                a[mt][3] = As2[m + 8][khb + 4 + qc];
            }
            #pragma unroll
            for (int nt = 0; nt < 4; nt++) {
                int n = warpN + nt * 8 + qr;
                b[nt][0] = Bs2[n][khb + qc];
                b[nt][1] = Bs2[n][khb + 4 + qc];
            }
            #pragma unroll
            for (int mt = 0; mt < 4; mt++)
                #pragma unroll
                for (int nt = 0; nt < 4; nt++)
                    mma16816(d[mt][nt], a[mt], b[nt]);
        }
    }

    #pragma unroll
    for (int mt = 0; mt < 4; mt++) {
        #pragma unroll
        for (int nt = 0; nt < 4; nt++) {
            int r0 = by * 128 + warpM + mt * 16 + qr;
            int c0 = bx * 128 + warpN + nt * 8 + qc * 2;
            *(__half2*)&g_simh[(size_t)r0 * N_NODES + c0] =
                __floats2half2_rn(d[mt][nt][0], d[mt][nt][1]);
            *(__half2*)&g_simh[(size_t)(r0 + 8) * N_NODES + c0] =
                __floats2half2_rn(d[mt][nt][2], d[mt][nt][3]);
            if (bx != by) {
                g_simh[(size_t)c0 * N_NODES + r0]           = __float2half_rn(d[mt][nt][0]);
                g_simh[(size_t)(c0 + 1) * N_NODES + r0]     = __float2half_rn(d[mt][nt][1]);
                g_simh[(size_t)c0 * N_NODES + r0 + 8]       = __float2half_rn(d[mt][nt][2]);
                g_simh[(size_t)(c0 + 1) * N_NODES + r0 + 8] = __float2half_rn(d[mt][nt][3]);
            }
        }
    }
}

// ------------- histogram select: per-row approx top-NTGT candidate set ------
__device__ __forceinline__ int half_key(uint32_t h) {   // monotonic 16-bit key
    return (h & 0x8000u) ? (int)(~h & 0xFFFFu) : (int)(h | 0x8000u);
}

__global__ __launch_bounds__(256) void select_kernel() {
    __shared__ uint32_t hist[1024];
    __shared__ uint32_t subh[64];
    __shared__ int s_B, s_base, s_cutKey;
    __shared__ int s_ctr;

    int row = blockIdx.x;
    int t   = threadIdx.x;

    for (int i = t; i < 1024; i += 256) hist[i] = 0;
    if (t < 64) subh[t] = 0;
    if (t == 0) s_ctr = 0;
    __syncthreads();

    // load 32 halves into registers, build keys
    const uint4* rp = (const uint4*)(g_simh + (size_t)row * N_NODES);
    int key[32];
    #pragma unroll
    for (int m = 0; m < 4; m++) {
        uint4 v = rp[t + 256 * m];
        uint32_t u[4] = {v.x, v.y, v.z, v.w};
        #pragma unroll
        for (int q = 0; q < 4; q++) {
            key[m * 8 + q * 2]     = half_key(u[q] & 0xFFFFu);
            key[m * 8 + q * 2 + 1] = half_key(u[q] >> 16);
        }
    }
    #pragma unroll
    for (int j = 0; j < 32; j++) atomicAdd(&hist[key[j] >> 6], 1u);
    __syncthreads();

    // warp 0: suffix scan over 1024 buckets, find cutoff bucket B
    if (t < 32) {
        uint32_t s = 0;
        #pragma unroll
        for (int i = 0; i < 32; i++) s += hist[t * 32 + i];
        uint32_t suf = s;
        #pragma unroll
        for (int o = 1; o < 32; o <<= 1) {
            uint32_t v = __shfl_down_sync(0xffffffffu, suf, o);
            if (t + o < 32) suf += v;
        }
        uint32_t above_lane = suf - s;
        if (suf >= NTGT && above_lane < NTGT) {
            uint32_t cum = above_lane;
            for (int i = 31; i >= 0; i--) {
                cum += hist[t * 32 + i];
                if (cum >= NTGT) {
                    s_B    = t * 32 + i;
                    s_base = (int)(cum - hist[t * 32 + i]);
                    break;
                }
            }
        }
    }
    __syncthreads();
    int B = s_B;

    // sub-histogram of low 6 bits within bucket B
    #pragma unroll
    for (int j = 0; j < 32; j++)
        if ((key[j] >> 6) == B) atomicAdd(&subh[key[j] & 63], 1u);
    __syncthreads();
    if (t == 0) {
        int cum = s_base;
        for (int s = 63; s >= 0; s--) {
            cum += (int)subh[s];
            if (cum >= NTGT) { s_cutKey = (B << 6) | s; break; }
        }
    }
    __syncthreads();
    int cutKey = s_cutKey;

    // collect all indices with key >= cutKey
    #pragma unroll
    for (int m = 0; m < 4; m++) {
        #pragma unroll
        for (int q = 0; q < 8; q++) {
            int j = m * 8 + q;
            if (key[j] >= cutKey) {
                int slot = atomicAdd(&s_ctr, 1);
                if (slot < NCAP)
                    g_cand[(size_t)row * NCAP + slot] = (t + 256 * m) * 8 + q;
            }
        }
    }
    __syncthreads();
    if (t == 0) g_ccnt[row] = min(s_ctr, NCAP);
}

// ------------- exact rescore (bit-exact ascending-k chain) + exact top-31 ---
__global__ __launch_bounds__(128) void rescore_kernel() {
    __shared__ float srow[D_FEAT];
    __shared__ float cval[NCAP];
    __shared__ int   ccol[NCAP];
    __shared__ int   scnt;

    int row = blockIdx.x;
    int t   = threadIdx.x;

    ((float4*)srow)[t] = ((const float4*)(g_xn + (size_t)row * D_FEAT))[t];
    if (t == 0) scnt = g_ccnt[row];
    if (t < NCAP) { cval[t] = -CUDART_INF_F; ccol[t] = 0x7fffffff; }
    __syncthreads();

    int cnt = scnt;
    if (t < cnt) {
        int c = g_cand[(size_t)row * NCAP + t];
        ccol[t] = c;
        const float4* cp = (const float4*)(g_xn + (size_t)c * D_FEAT);
        float acc = 0.f;
        #pragma unroll 8
        for (int k4 = 0; k4 < D_FEAT / 4; k4++) {
            float4 v = cp[k4];
            acc = fmaf(srow[4 * k4 + 0], v.x, acc);
            acc = fmaf(srow[4 * k4 + 1], v.y, acc);
            acc = fmaf(srow[4 * k4 + 2], v.z, acc);
            acc = fmaf(srow[4 * k4 + 3], v.w, acc);
        }
        cval[t] = acc;
    }
    __syncthreads();

    // warp 0: exact top-31 of up to 64 (value desc, col asc)
    if (t < 32) {
        for (int p = 0; p < KP1; p++) {
            float v0 = cval[t];      int c0 = ccol[t],      s0 = t;
            float v1 = cval[t + 32]; int c1 = ccol[t + 32], s1 = t + 32;
            float bv; int bc, bs;
            if (v0 > v1 || (v0 == v1 && c0 < c1)) { bv = v0; bc = c0; bs = s0; }
            else                                  { bv = v1; bc = c1; bs = s1; }
            #pragma unroll
            for (int o = 16; o; o >>= 1) {
                float ov = __shfl_down_sync(0xffffffffu, bv, o);
                int   oc = __shfl_down_sync(0xffffffffu, bc, o);
                int   os = __shfl_down_sync(0xffffffffu, bs, o);
                if (ov > bv || (ov == bv && oc < bc)) { bv = ov; bc = oc; bs = os; }
            }
            bv = __shfl_sync(0xffffffffu, bv, 0);
            bc = __shfl_sync(0xffffffffu, bc, 0);
            bs = __shfl_sync(0xffffffffu, bs, 0);
            if (t == 0) {
                g_vals[row * KP1 + p] = bv;
                g_inds[row * KP1 + p] = bc;
                cval[bs] = -CUDART_INF_F;
            }
            __syncwarp();
        }
    }
}

// ---------------- degree mass ----------------
__global__ void norm_accum_kernel() {
    int i = blockIdx.x * blockDim.x + threadIdx.x;
    if (i >= HALF_E) return;
    int   r = i / KP1;
    int   c = g_inds[i];
    float v = g_vals[i];
    atomicAdd(&g_norm[r], v);
    atomicAdd(&g_norm[c], v);
}

// ---------------- zero 256MB adjacency ----------------
__global__ void zero_adj_kernel(float* __restrict__ adj) {
    size_t i = (size_t)blockIdx.x * blockDim.x + threadIdx.x;
    ((float4*)adj)[i] = make_float4(0.f, 0.f, 0.f, 0.f);
}

// ---------------- JAX threefry2x32, key = (0, 42) ----------------
__device__ __forceinline__ uint32_t rotl32(uint32_t v, int d) {
    return (v << d) | (v >> (32 - d));
}
__device__ __forceinline__ void threefry2x32_42(uint32_t c0, uint32_t c1,
                                                uint32_t& o0, uint32_t& o1) {
    const uint32_t ks0 = 0u, ks1 = 42u, ks2 = 0u ^ 42u ^ 0x1BD11BDAu;
    uint32_t x0 = c0 + ks0, x1 = c1 + ks1;
    const int ra[4] = {13, 15, 26, 6};
    const int rb[4] = {17, 29, 16, 24};
    #pragma unroll
    for (int i = 0; i < 4; i++) { x0 += x1; x1 = rotl32(x1, ra[i]); x1 ^= x0; }
    x0 += ks1; x1 += ks2 + 1u;
    #pragma unroll
    for (int i = 0; i < 4; i++) { x0 += x1; x1 = rotl32(x1, rb[i]); x1 ^= x0; }
    x0 += ks2; x1 += ks0 + 2u;
    #pragma unroll
    for (int i = 0; i < 4; i++) { x0 += x1; x1 = rotl32(x1, ra[i]); x1 ^= x0; }
    x0 += ks0; x1 += ks1 + 3u;
    #pragma unroll
    for (int i = 0; i < 4; i++) { x0 += x1; x1 = rotl32(x1, rb[i]); x1 ^= x0; }
    x0 += ks1; x1 += ks2 + 4u;
    #pragma unroll
    for (int i = 0; i < 4; i++) { x0 += x1; x1 = rotl32(x1, ra[i]); x1 ^= x0; }
    x0 += ks2; x1 += ks0 + 5u;
    o0 = x0; o1 = x1;
}
__device__ __forceinline__ bool keep_edge(uint32_t i) {
    uint32_t o0, o1;
    threefry2x32_42(0u, i, o0, o1);
    uint32_t b = o0 ^ o1;
    float u = __uint_as_float((b >> 9) | 0x3f800000u) - 1.0f;
    return u < 0.9f;
}

// ---------------- normalize edges + dropout + symmetric scatter-add ----------
__global__ void scatter_kernel(float* __restrict__ adj) {
    int i = blockIdx.x * blockDim.x + threadIdx.x;
    if (i >= HALF_E) return;
    int   r = i / KP1;
    int   c = g_inds[i];
    float v = g_vals[i];
    float w = v * __frcp_rn(__fsqrt_rn(g_norm[r]));
    w = w * __frcp_rn(__fsqrt_rn(g_norm[c]));
    if (isnan(w)) w = 0.f;
    w = fmaxf(w, 0.f);

    float w0 = keep_edge((uint32_t)i)            ? (w / 0.9f) : 0.f;
    float w1 = keep_edge((uint32_t)(i + HALF_E)) ? (w / 0.9f) : 0.f;

    atomicAdd(&adj[(size_t)r * N_NODES + c], w0);
    atomicAdd(&adj[(size_t)c * N_NODES + r], w1);
}

// ---------------- launch ----------------
extern "C" void kernel_launch(void* const* d_in, const int* in_sizes, int n_in,
                              void* d_out, int out_size) {
    const float* x  = (const float*)d_in[0];
    float* adj = (float*)d_out;
    (void)in_sizes; (void)n_in; (void)out_size;

    normalize_kernel<<<N_NODES, 128>>>(x);

    dim3 ggrid(N_NODES / 128, N_NODES / 128);
    hgemm_sym_kernel<<<ggrid, 256>>>();

    select_kernel<<<N_NODES, 256>>>();
    rescore_kernel<<<N_NODES, 128>>>();

    norm_accum_kernel<<<(HALF_E + 255) / 256, 256>>>();

    zero_adj_kernel<<<(N_NODES * (N_NODES / 4)) / 256, 256>>>(adj);
    scatter_kernel<<<(HALF_E + 255) / 256, 256>>>(adj);
}

// round 9
// speedup vs baseline: 2.8767x; 1.1469x over previous
#include <cuda_runtime.h>
#include <cuda_fp16.h>
#include <cuda_bf16.h>
#include <cstdint>
#include <math_constants.h>

#define N_NODES 8192
#define D_FEAT  512
#define KNN     30
#define KP1     31
#define NTGT    36      // approx-rank margin target
#define NCAP    64      // candidate array capacity
#define HALF_E  (N_NODES * KP1)
#define KB      64      // rescore k-batch
#define NB      (D_FEAT / KB)

// ---------------- static device scratch (no allocs allowed) ----------------
__device__ float  g_xn[(size_t)N_NODES * D_FEAT];                     // 16 MB
__device__ __align__(16) __half g_xh[(size_t)N_NODES * D_FEAT];       // 8 MB
__device__ __align__(16) __half g_simh[(size_t)N_NODES * N_NODES];    // 128 MB
__device__ int    g_cand[(size_t)N_NODES * NCAP];
__device__ int    g_ccnt[N_NODES];
__device__ float  g_vals[(size_t)N_NODES * KP1];
__device__ int    g_inds[(size_t)N_NODES * KP1];
__device__ float  g_norm[N_NODES];

// ---------------- row normalize: xn = x/||x|| (IEEE fp32) + fp16 copy -------
__global__ void normalize_kernel(const float* __restrict__ x) {
    int row = blockIdx.x;
    int t   = threadIdx.x;                 // 128 threads, 4 floats each
    if (t == 0) g_norm[row] = 0.f;
    const float4* xr = (const float4*)(x + (size_t)row * D_FEAT);
    float4 v = xr[t];
    float ss = v.x * v.x + v.y * v.y + v.z * v.z + v.w * v.w;
    #pragma unroll
    for (int o = 16; o; o >>= 1) ss += __shfl_down_sync(0xffffffffu, ss, o);
    __shared__ float ws[4];
    if ((t & 31) == 0) ws[t >> 5] = ss;
    __syncthreads();
    float nrm = __fsqrt_rn(ws[0] + ws[1] + ws[2] + ws[3]);
    float4 o4;
    o4.x = __fdiv_rn(v.x, nrm); o4.y = __fdiv_rn(v.y, nrm);
    o4.z = __fdiv_rn(v.z, nrm); o4.w = __fdiv_rn(v.w, nrm);
    ((float4*)(g_xn + (size_t)row * D_FEAT))[t] = o4;
    __half2* hp = (__half2*)(g_xh + (size_t)row * D_FEAT);
    hp[t * 2]     = __floats2half2_rn(o4.x, o4.y);
    hp[t * 2 + 1] = __floats2half2_rn(o4.z, o4.w);
}

// ------------- approx symmetric GEMM: fp16 HMMA, fp32 accum, fp16 out -------
__device__ __forceinline__ void mma16816(float* d, const uint32_t* a, const uint32_t* b) {
    asm volatile(
        "mma.sync.aligned.m16n8k16.row.col.f32.f16.f16.f32 "
        "{%0,%1,%2,%3}, {%4,%5,%6,%7}, {%8,%9}, {%0,%1,%2,%3};"
        : "+f"(d[0]), "+f"(d[1]), "+f"(d[2]), "+f"(d[3])
        : "r"(a[0]), "r"(a[1]), "r"(a[2]), "r"(a[3]), "r"(b[0]), "r"(b[1]));
}

#define HPITCH 20
__global__ __launch_bounds__(256) void hgemm_sym_kernel() {
    int bx = blockIdx.x, by = blockIdx.y;
    if (bx > by) return;

    __shared__ __align__(16) uint32_t As2[128][HPITCH];
    __shared__ __align__(16) uint32_t Bs2[128][HPITCH];

    int t = threadIdx.x, lane = t & 31, w = t >> 5;
    int warpM = (w & 1) * 64, warpN = (w >> 1) * 32;
    int qr = lane >> 2, qc = lane & 3;

    const __half* Ag = g_xh + (size_t)(by * 128) * D_FEAT;
    const __half* Bg = g_xh + (size_t)(bx * 128) * D_FEAT;

    float d[4][4][4];
    #pragma unroll
    for (int i = 0; i < 4; i++)
        #pragma unroll
        for (int j = 0; j < 4; j++)
            #pragma unroll
            for (int c = 0; c < 4; c++) d[i][j][c] = 0.f;

    for (int k0 = 0; k0 < D_FEAT; k0 += 32) {
        __syncthreads();
        #pragma unroll
        for (int it = 0; it < 2; it++) {
            int idx  = t + it * 256;
            int node = idx >> 2;
            int koff = (idx & 3) * 8;
            uint4 va = *(const uint4*)(Ag + (size_t)node * D_FEAT + k0 + koff);
            *(uint4*)&As2[node][koff >> 1] = va;
            uint4 vb = *(const uint4*)(Bg + (size_t)node * D_FEAT + k0 + koff);
            *(uint4*)&Bs2[node][koff >> 1] = vb;
        }
        __syncthreads();
        #pragma unroll
        for (int kb = 0; kb < 2; kb++) {
            int khb = kb * 8;
            uint32_t a[4][4], b[4][2];
            #pragma unroll
            for (int mt = 0; mt < 4; mt++) {
                int m = warpM + mt * 16 + qr;
                a[mt][0] = As2[m][khb + qc];
                a[mt][1] = As2[m + 8][khb + qc];
                a[mt][2] = As2[m][khb + 4 + qc];
                a[mt][3] = As2[m + 8][khb + 4 + qc];
            }
            #pragma unroll
            for (int nt = 0; nt < 4; nt++) {
                int n = warpN + nt * 8 + qr;
                b[nt][0] = Bs2[n][khb + qc];
                b[nt][1] = Bs2[n][khb + 4 + qc];
            }
            #pragma unroll
            for (int mt = 0; mt < 4; mt++)
                #pragma unroll
                for (int nt = 0; nt < 4; nt++)
                    mma16816(d[mt][nt], a[mt], b[nt]);
        }
    }

    #pragma unroll
    for (int mt = 0; mt < 4; mt++) {
        #pragma unroll
        for (int nt = 0; nt < 4; nt++) {
            int r0 = by * 128 + warpM + mt * 16 + qr;
            int c0 = bx * 128 + warpN + nt * 8 + qc * 2;
            *(__half2*)&g_simh[(size_t)r0 * N_NODES + c0] =
                __floats2half2_rn(d[mt][nt][0], d[mt][nt][1]);
            *(__half2*)&g_simh[(size_t)(r0 + 8) * N_NODES + c0] =
                __floats2half2_rn(d[mt][nt][2], d[mt][nt][3]);
            if (bx != by) {
                g_simh[(size_t)c0 * N_NODES + r0]           = __float2half_rn(d[mt][nt][0]);
                g_simh[(size_t)(c0 + 1) * N_NODES + r0]     = __float2half_rn(d[mt][nt][1]);
                g_simh[(size_t)c0 * N_NODES + r0 + 8]       = __float2half_rn(d[mt][nt][2]);
                g_simh[(size_t)(c0 + 1) * N_NODES + r0 + 8] = __float2half_rn(d[mt][nt][3]);
            }
        }
    }
}

// ------------- histogram select: per-row approx top-NTGT candidate set ------
__device__ __forceinline__ int half_key(uint32_t h) {   // monotonic 16-bit key
    return (h & 0x8000u) ? (int)(~h & 0xFFFFu) : (int)(h | 0x8000u);
}

__global__ __launch_bounds__(256) void select_kernel() {
    __shared__ uint32_t hist[1024];
    __shared__ uint32_t subh[64];
    __shared__ int s_B, s_base, s_cutKey;
    __shared__ int s_ctr;

    int row = blockIdx.x;
    int t   = threadIdx.x;

    for (int i = t; i < 1024; i += 256) hist[i] = 0;
    if (t < 64) subh[t] = 0;
    if (t == 0) s_ctr = 0;
    __syncthreads();

    const uint4* rp = (const uint4*)(g_simh + (size_t)row * N_NODES);
    int key[32];
    #pragma unroll
    for (int m = 0; m < 4; m++) {
        uint4 v = rp[t + 256 * m];
        uint32_t u[4] = {v.x, v.y, v.z, v.w};
        #pragma unroll
        for (int q = 0; q < 4; q++) {
            key[m * 8 + q * 2]     = half_key(u[q] & 0xFFFFu);
            key[m * 8 + q * 2 + 1] = half_key(u[q] >> 16);
        }
    }
    #pragma unroll
    for (int j = 0; j < 32; j++) atomicAdd(&hist[key[j] >> 6], 1u);
    __syncthreads();

    if (t < 32) {
        uint32_t s = 0;
        #pragma unroll
        for (int i = 0; i < 32; i++) s += hist[t * 32 + i];
        uint32_t suf = s;
        #pragma unroll
        for (int o = 1; o < 32; o <<= 1) {
            uint32_t v = __shfl_down_sync(0xffffffffu, suf, o);
            if (t + o < 32) suf += v;
        }
        uint32_t above_lane = suf - s;
        if (suf >= NTGT && above_lane < NTGT) {
            uint32_t cum = above_lane;
            for (int i = 31; i >= 0; i--) {
                cum += hist[t * 32 + i];
                if (cum >= NTGT) {
                    s_B    = t * 32 + i;
                    s_base = (int)(cum - hist[t * 32 + i]);
                    break;
                }
            }
        }
    }
    __syncthreads();
    int B = s_B;

    #pragma unroll
    for (int j = 0; j < 32; j++)
        if ((key[j] >> 6) == B) atomicAdd(&subh[key[j] & 63], 1u);
    __syncthreads();
    if (t == 0) {
        int cum = s_base;
        for (int s = 63; s >= 0; s--) {
            cum += (int)subh[s];
            if (cum >= NTGT) { s_cutKey = (B << 6) | s; break; }
        }
    }
    __syncthreads();
    int cutKey = s_cutKey;

    #pragma unroll
    for (int m = 0; m < 4; m++) {
        #pragma unroll
        for (int q = 0; q < 8; q++) {
            int j = m * 8 + q;
            if (key[j] >= cutKey) {
                int slot = atomicAdd(&s_ctr, 1);
                if (slot < NCAP)
                    g_cand[(size_t)row * NCAP + slot] = (t + 256 * m) * 8 + q;
            }
        }
    }
    __syncthreads();
    if (t == 0) g_ccnt[row] = min(s_ctr, NCAP);
}

// ------------- exact rescore: k-batched smem staging, bit-exact chain -------
// + exact top-31 + fused degree-mass accumulation
__global__ __launch_bounds__(128) void rescore_kernel() {
    __shared__ float srow[D_FEAT];            // 2 KB
    __shared__ float scolT[KB][NCAP + 1];     // 64 x 65 x 4B = 16.6 KB, transposed
    __shared__ float cval[NCAP];
    __shared__ int   ccol[NCAP];
    __shared__ int   scnt;

    int row = blockIdx.x;
    int t   = threadIdx.x;

    ((float4*)srow)[t] = ((const float4*)(g_xn + (size_t)row * D_FEAT))[t];
    if (t == 0) scnt = g_ccnt[row];
    if (t < NCAP) { cval[t] = -CUDART_INF_F; ccol[t] = 0x7fffffff; }
    __syncthreads();
    int cnt = scnt;
    if (t < cnt) ccol[t] = g_cand[(size_t)row * NCAP + t];
    __syncthreads();

    float acc = 0.f;
    int ci = t >> 3;          // column-group lane: 16 columns per pass
    int j  = t & 7;           // float4 index within k-batch (8 per col half)
    for (int b = 0; b < NB; b++) {
        __syncthreads();
        // coalesced stage: columns [0,cnt), k in [b*KB, b*KB+KB)
        for (int cg = ci; cg < cnt; cg += 16) {
            const float4* cp = (const float4*)(g_xn + (size_t)ccol[cg] * D_FEAT + b * KB);
            float4 v0 = cp[j];
            float4 v1 = cp[j + 8];
            int k0 = j * 4, k1 = (j + 8) * 4;
            scolT[k0 + 0][cg] = v0.x; scolT[k0 + 1][cg] = v0.y;
            scolT[k0 + 2][cg] = v0.z; scolT[k0 + 3][cg] = v0.w;
            scolT[k1 + 0][cg] = v1.x; scolT[k1 + 1][cg] = v1.y;
            scolT[k1 + 2][cg] = v1.z; scolT[k1 + 3][cg] = v1.w;
        }
        __syncthreads();
        if (t < cnt) {
            #pragma unroll 16
            for (int kk = 0; kk < KB; kk++)
                acc = fmaf(srow[b * KB + kk], scolT[kk][t], acc);  // exact ascending-k chain
        }
    }
    if (t < cnt) cval[t] = acc;
    __syncthreads();

    // warp 0: exact top-31 of up to 64 (value desc, col asc) + norm accumulation
    if (t < 32) {
        float rowsum = 0.f;
        for (int p = 0; p < KP1; p++) {
            float v0 = cval[t];      int c0 = ccol[t],      s0 = t;
            float v1 = cval[t + 32]; int c1 = ccol[t + 32], s1 = t + 32;
            float bv; int bc, bs;
            if (v0 > v1 || (v0 == v1 && c0 < c1)) { bv = v0; bc = c0; bs = s0; }
            else                                  { bv = v1; bc = c1; bs = s1; }
            #pragma unroll
            for (int o = 16; o; o >>= 1) {
                float ov = __shfl_down_sync(0xffffffffu, bv, o);
                int   oc = __shfl_down_sync(0xffffffffu, bc, o);
                int   os = __shfl_down_sync(0xffffffffu, bs, o);
                if (ov > bv || (ov == bv && oc < bc)) { bv = ov; bc = oc; bs = os; }
            }
            bv = __shfl_sync(0xffffffffu, bv, 0);
            bc = __shfl_sync(0xffffffffu, bc, 0);
            bs = __shfl_sync(0xffffffffu, bs, 0);
            if (t == 0) {
                g_vals[row * KP1 + p] = bv;
                g_inds[row * KP1 + p] = bc;
                cval[bs] = -CUDART_INF_F;
                rowsum += bv;
                atomicAdd(&g_norm[bc], bv);      // in-degree mass
            }
            __syncwarp();
        }
        if (t == 0) atomicAdd(&g_norm[row], rowsum);  // out-degree mass
    }
}

// ---------------- zero 256MB adjacency ----------------
__global__ void zero_adj_kernel(float* __restrict__ adj) {
    size_t i = (size_t)blockIdx.x * blockDim.x + threadIdx.x;
    ((float4*)adj)[i] = make_float4(0.f, 0.f, 0.f, 0.f);
}

// ---------------- JAX threefry2x32, key = (0, 42) ----------------
__device__ __forceinline__ uint32_t rotl32(uint32_t v, int d) {
    return (v << d) | (v >> (32 - d));
}
__device__ __forceinline__ void threefry2x32_42(uint32_t c0, uint32_t c1,
                                                uint32_t& o0, uint32_t& o1) {
    const uint32_t ks0 = 0u, ks1 = 42u, ks2 = 0u ^ 42u ^ 0x1BD11BDAu;
    uint32_t x0 = c0 + ks0, x1 = c1 + ks1;
    const int ra[4] = {13, 15, 26, 6};
    const int rb[4] = {17, 29, 16, 24};
    #pragma unroll
    for (int i = 0; i < 4; i++) { x0 += x1; x1 = rotl32(x1, ra[i]); x1 ^= x0; }
    x0 += ks1; x1 += ks2 + 1u;
    #pragma unroll
    for (int i = 0; i < 4; i++) { x0 += x1; x1 = rotl32(x1, rb[i]); x1 ^= x0; }
    x0 += ks2; x1 += ks0 + 2u;
    #pragma unroll
    for (int i = 0; i < 4; i++) { x0 += x1; x1 = rotl32(x1, ra[i]); x1 ^= x0; }
    x0 += ks0; x1 += ks1 + 3u;
    #pragma unroll
    for (int i = 0; i < 4; i++) { x0 += x1; x1 = rotl32(x1, rb[i]); x1 ^= x0; }
    x0 += ks1; x1 += ks2 + 4u;
    #pragma unroll
    for (int i = 0; i < 4; i++) { x0 += x1; x1 = rotl32(x1, ra[i]); x1 ^= x0; }
    x0 += ks2; x1 += ks0 + 5u;
    o0 = x0; o1 = x1;
}
__device__ __forceinline__ bool keep_edge(uint32_t i) {
    uint32_t o0, o1;
    threefry2x32_42(0u, i, o0, o1);
    uint32_t b = o0 ^ o1;
    float u = __uint_as_float((b >> 9) | 0x3f800000u) - 1.0f;
    return u < 0.9f;
}

// ---------------- normalize edges + dropout + symmetric scatter-add ----------
__global__ void scatter_kernel(float* __restrict__ adj) {
    int i = blockIdx.x * blockDim.x + threadIdx.x;
    if (i >= HALF_E) return;
    int   r = i / KP1;
    int   c = g_inds[i];
    float v = g_vals[i];
    float w = v * __frcp_rn(__fsqrt_rn(g_norm[r]));
    w = w * __frcp_rn(__fsqrt_rn(g_norm[c]));
    if (isnan(w)) w = 0.f;
    w = fmaxf(w, 0.f);

    float w0 = keep_edge((uint32_t)i)            ? (w / 0.9f) : 0.f;
    float w1 = keep_edge((uint32_t)(i + HALF_E)) ? (w / 0.9f) : 0.f;

    atomicAdd(&adj[(size_t)r * N_NODES + c], w0);
    atomicAdd(&adj[(size_t)c * N_NODES + r], w1);
}

// ---------------- launch ----------------
extern "C" void kernel_launch(void* const* d_in, const int* in_sizes, int n_in,
                              void* d_out, int out_size) {
    const float* x  = (const float*)d_in[0];
    float* adj = (float*)d_out;
    (void)in_sizes; (void)n_in; (void)out_size;

    normalize_kernel<<<N_NODES, 128>>>(x);

    dim3 ggrid(N_NODES / 128, N_NODES / 128);
    hgemm_sym_kernel<<<ggrid, 256>>>();

    select_kernel<<<N_NODES, 256>>>();
    rescore_kernel<<<N_NODES, 128>>>();

    zero_adj_kernel<<<(N_NODES * (N_NODES / 4)) / 256, 256>>>(adj);
    scatter_kernel<<<(HALF_E + 255) / 256, 256>>>(adj);
}